// round 6
// baseline (speedup 1.0000x reference)
#include <cuda_runtime.h>
#include <cuda_bf16.h>

#define NQ      65536
#define PP      2048
#define NT      32                // tiles per side (256/8)
#define NTILES  1024
#define CAPQ    256               // queries per tile bucket (mean 64, sd 8)
#define CAPT    192               // kept nodes per tile (mean ~40)
#define GRID    148               // one wave, all resident (barrier-safe)
#define NTHR    256
#define LOG2E   1.4426950408889634f
#define THRESH  26.0f             // log2 cut: dropped mass <= 2048*2^-26

// Static device state (zero-initialized at module load).
__device__ int      g_qcnt[NTILES];
__device__ unsigned g_qdat[NTILES * CAPQ];   // packed q<<16 | y<<8 | x
__device__ unsigned g_arrive;
__device__ unsigned g_done;

__device__ __forceinline__ float ex2f(float x) {
    float r; asm("ex2.approx.f32 %0,%1;" : "=f"(r) : "f"(x)); return r;
}

__global__ __launch_bounds__(NTHR, 1)
void k_all(const int2* __restrict__ X,
           const int2* __restrict__ pat,
           const float* __restrict__ W2,
           const float* __restrict__ sig,
           float* __restrict__ out) {
    __shared__ float4 pc[PP];            // {p0, p1, C, 0}  32 KB
    __shared__ float4 rec[2 * CAPT];     // kept eval records  6 KB
    __shared__ int    idx[CAPT];
    __shared__ float4 red[NTHR];         // eval partial reduce  4 KB
    __shared__ float  warpmax[8];
    __shared__ int    wcnt[8];
    __shared__ float  s_cut;

    const int tid  = threadIdx.x;
    const int lane = tid & 31;
    const int wrp  = tid >> 5;

    // ---- Phase 0a: scatter queries into per-tile buckets ----
    for (int i = blockIdx.x * NTHR + tid; i < NQ; i += GRID * NTHR) {
        int2 xy = X[i];
        int t = (xy.x >> 3) * NT + (xy.y >> 3);
        int pos = atomicAdd(&g_qcnt[t], 1);
        if (pos < CAPQ)
            g_qdat[t * CAPQ + pos] =
                ((unsigned)i << 16) | ((unsigned)xy.y << 8) | (unsigned)xy.x;
    }

    // ---- Phase 0b: stage node table {p0,p1,C} into smem ----
    for (int i = tid; i < PP; i += NTHR) {
        int2 p = pat[i];
        float C = -__fdividef(LOG2E, 2.0f * sig[i]);   // negative
        pc[i] = make_float4((float)p.x, (float)p.y, C, 0.0f);
    }

    // ---- Grid barrier (all 148 CTAs resident by construction) ----
    __syncthreads();
    if (tid == 0) {
        __threadfence();
        atomicAdd(&g_arrive, 1);
        while (*(volatile unsigned*)&g_arrive < GRID) {}
        __threadfence();
    }
    __syncthreads();

    // ---- Tile loop: ~7 tiles per CTA ----
    for (int t = blockIdx.x; t < NTILES; t += GRID) {
        int cnt = g_qcnt[t];
        if (cnt == 0) continue;              // uniform across CTA
        if (cnt > CAPQ) cnt = CAPQ;

        float tx0 = (float)((t >> 5) << 3), ty0 = (float)((t & 31) << 3);
        float tx1 = tx0 + 7.0f, ty1 = ty0 + 7.0f;

        // Phase A: best = max_p C_p * dmax^2 (achievable max-log2 bound)
        float best = -1e30f;
#pragma unroll
        for (int i = tid; i < PP; i += NTHR) {
            float4 p = pc[i];
            float dx = fmaxf(fabsf(p.x - tx0), fabsf(p.x - tx1));
            float dy = fmaxf(fabsf(p.y - ty0), fabsf(p.y - ty1));
            best = fmaxf(best, p.z * fmaf(dx, dx, dy * dy));
        }
        for (int o = 16; o; o >>= 1)
            best = fmaxf(best, __shfl_xor_sync(0xffffffffu, best, o));
        if (lane == 0) warpmax[wrp] = best;
        __syncthreads();
        if (tid == 0) {
            float b = warpmax[0];
#pragma unroll
            for (int w = 1; w < 8; w++) b = fmaxf(b, warpmax[w]);
            s_cut = b - THRESH;
        }
        __syncthreads();
        float cut = s_cut;

        // Phase B pass 1: per-warp keep counts (warp w owns nodes [256w,256w+256))
        int mycnt = 0;
#pragma unroll
        for (int r = 0; r < 8; r++) {
            int p = wrp * 256 + r * 32 + lane;
            float4 v = pc[p];
            float dx = fmaxf(fmaxf(tx0 - v.x, v.x - tx1), 0.0f);
            float dy = fmaxf(fmaxf(ty0 - v.y, v.y - ty1), 0.0f);
            bool keep = (v.z * fmaf(dx, dx, dy * dy) >= cut);
            mycnt += __popc(__ballot_sync(0xffffffffu, keep));
        }
        if (lane == 0) wcnt[wrp] = mycnt;
        __syncthreads();
        int base = 0;
#pragma unroll
        for (int w = 0; w < 8; w++) { if (w < wrp) base += wcnt[w]; }
        int nk = base;                        // recompute total below
        {
            int tot = 0;
#pragma unroll
            for (int w = 0; w < 8; w++) tot += wcnt[w];
            nk = tot < CAPT ? tot : CAPT;
        }
        // Phase B pass 2: write kept node indices (ascending, deterministic)
#pragma unroll
        for (int r = 0; r < 8; r++) {
            int p = wrp * 256 + r * 32 + lane;
            float4 v = pc[p];
            float dx = fmaxf(fmaxf(tx0 - v.x, v.x - tx1), 0.0f);
            float dy = fmaxf(fmaxf(ty0 - v.y, v.y - ty1), 0.0f);
            bool keep = (v.z * fmaf(dx, dx, dy * dy) >= cut);
            unsigned m = __ballot_sync(0xffffffffu, keep);
            if (keep) {
                int r2 = base + __popc(m & ((1u << lane) - 1u));
                if (r2 < CAPT) idx[r2] = p;
            }
            base += __popc(m);
        }
        __syncthreads();

        // Gather eval records into smem (one thread per kept node)
        if (tid < nk) {
            int p = idx[tid];
            float4 v = pc[p];
            float C = v.z;
            rec[2 * tid] = make_float4(-2.0f * C * v.x, -2.0f * C * v.y,
                                       C * fmaf(v.x, v.x, v.y * v.y), C);
            rec[2 * tid + 1] = make_float4(W2[p], W2[PP + p], W2[2 * PP + p], 0.f);
        }
        __syncthreads();

        // Phase C: eval. 64 query slots x 4 node chunks.
        int chunk = tid >> 6;
        int qslot = tid & 63;
        for (int qb = 0; qb < cnt; qb += 64) {
            int qi = qb + qslot;
            float4 acc = make_float4(0.f, 0.f, 0.f, 0.f);
            if (qi < cnt) {
                unsigned d = g_qdat[t * CAPQ + qi];
                float x0 = (float)(d & 255u);
                float x1 = (float)((d >> 8) & 255u);
                float xx = fmaf(x0, x0, x1 * x1);
#pragma unroll 4
                for (int j = chunk; j < nk; j += 4) {
                    float4 a = rec[2 * j];
                    float4 b = rec[2 * j + 1];
                    float arg = fmaf(a.w, xx, a.z);
                    arg = fmaf(a.x, x0, arg);
                    arg = fmaf(a.y, x1, arg);
                    float e = ex2f(arg);
                    acc.x += e;
                    acc.y = fmaf(e, b.x, acc.y);
                    acc.z = fmaf(e, b.y, acc.z);
                    acc.w = fmaf(e, b.z, acc.w);
                }
            }
            red[tid] = acc;
            __syncthreads();
            if (tid < 64 && qb + tid < cnt) {
                float4 a0 = red[tid];
                float4 a1 = red[64 + tid];
                float4 a2 = red[128 + tid];
                float4 a3 = red[192 + tid];
                float den = (a0.x + a1.x) + (a2.x + a3.x);
                float n0  = (a0.y + a1.y) + (a2.y + a3.y);
                float n1  = (a0.z + a1.z) + (a2.z + a3.z);
                float n2  = (a0.w + a1.w) + (a2.w + a3.w);
                float inv = 1.0f / den;
                int q = (int)(g_qdat[t * CAPQ + qb + tid] >> 16);
                out[3 * q + 0] = n0 * inv;
                out[3 * q + 1] = n1 * inv;
                out[3 * q + 2] = n2 * inv;
            }
            __syncthreads();
        }
        if (tid == 0) g_qcnt[t] = 0;          // reset bucket for next replay
        __syncthreads();
    }

    // ---- Epilogue: last CTA resets barrier state for next graph replay ----
    __syncthreads();
    if (tid == 0) {
        __threadfence();
        unsigned old = atomicAdd(&g_done, 1);
        if (old == GRID - 1) {
            g_arrive = 0;
            g_done = 0;
            __threadfence();
        }
    }
}

extern "C" void kernel_launch(void* const* d_in, const int* in_sizes, int n_in,
                              void* d_out, int out_size) {
    const int*   X   = (const int*)d_in[0];     // [N,2] int32
    const int*   pat = (const int*)d_in[1];     // [P,2] int32
    const float* W2  = (const float*)d_in[2];   // [C,P] f32
    const float* sig = (const float*)d_in[3];   // [P]   f32
    float* out = (float*)d_out;
    (void)in_sizes; (void)n_in; (void)out_size;

    k_all<<<GRID, NTHR>>>((const int2*)X, (const int2*)pat, W2, sig, out);
}

// round 7
// speedup vs baseline: 1.4719x; 1.4719x over previous
#include <cuda_runtime.h>
#include <cuda_bf16.h>

#define NQ      65536
#define PP      2048
#define NT      32                 // tiles per side (256/8)
#define NTILES  1024
#define CAPQ    256                // queries per tile bucket (mean 64, sd 8)
#define CAPT    256                // kept nodes per tile (mean ~40-70)
#define LOG2E   1.4426950408889634f
#define THRESH  26.0f              // log2 cut: dropped mass <= 2048*2^-26 ~ 3e-5

// Static device state (zero-initialized at module load; no allocation).
__device__ int      g_ncnt[NTILES];
__device__ float    g_list[(size_t)NTILES * CAPT * 8];   // 8 MB records
__device__ int      g_qcnt[NTILES];                      // reset by k_main tail
__device__ unsigned g_qdat[NTILES * CAPQ];               // packed q<<16|y<<8|x

__device__ __forceinline__ float ex2f(float x) {
    float r; asm("ex2.approx.f32 %0,%1;" : "=f"(r) : "f"(x)); return r;
}

// ---------------------------------------------------------------------------
// K1: one CTA per tile. Fuses: query scatter (64 queries/CTA), per-tile max
// bound, ballot compaction (deterministic ascending order), record gather.
// ---------------------------------------------------------------------------
__global__ __launch_bounds__(128)
void k_prep(const int2* __restrict__ X,
            const int2* __restrict__ pat,
            const float* __restrict__ W2,
            const float* __restrict__ sig) {
    __shared__ float4 pc[PP];        // {p0, p1, C, 0}  32 KB
    __shared__ int    idx[CAPT];
    __shared__ float  wmax[4];
    __shared__ int    wcnt[4];

    const int tid  = threadIdx.x;
    const int lane = tid & 31;
    const int wrp  = tid >> 5;
    const int t    = blockIdx.x;

    // -- Query scatter: this CTA owns queries [64t, 64t+64) --
    if (tid < 64) {
        int i = t * 64 + tid;
        int2 xy = X[i];
        int tt = (xy.x >> 3) * NT + (xy.y >> 3);
        int pos = atomicAdd(&g_qcnt[tt], 1);
        if (pos < CAPQ)
            g_qdat[tt * CAPQ + pos] =
                ((unsigned)i << 16) | ((unsigned)xy.y << 8) | (unsigned)xy.x;
    }

    const float tx0 = (float)((t >> 5) << 3), ty0 = (float)((t & 31) << 3);
    const float tx1 = tx0 + 7.0f, ty1 = ty0 + 7.0f;

    // -- Phase A: stage node constants + tile max bound (16 nodes/thread) --
    float best = -1e30f;
#pragma unroll
    for (int r = 0; r < PP / 128; r++) {
        int p = r * 128 + tid;
        int2 pp = pat[p];
        float px = (float)pp.x, py = (float)pp.y;
        float C = -LOG2E / (2.0f * sig[p]);            // negative
        pc[p] = make_float4(px, py, C, 0.0f);
        float dx = fmaxf(fabsf(px - tx0), fabsf(px - tx1));
        float dy = fmaxf(fabsf(py - ty0), fabsf(py - ty1));
        best = fmaxf(best, C * fmaf(dx, dx, dy * dy));
    }
    for (int o = 16; o; o >>= 1)
        best = fmaxf(best, __shfl_xor_sync(0xffffffffu, best, o));
    if (lane == 0) wmax[wrp] = best;
    __syncthreads();
    const float cut = fmaxf(fmaxf(wmax[0], wmax[1]),
                            fmaxf(wmax[2], wmax[3])) - THRESH;

    // -- Phase B: keep-mask (warp w owns nodes [512w,512w+512)), 16 rounds --
    unsigned masks[16];
    int mycnt = 0;
#pragma unroll
    for (int r = 0; r < 16; r++) {
        int p = wrp * 512 + r * 32 + lane;
        float4 v = pc[p];
        float dx = fmaxf(fmaxf(tx0 - v.x, v.x - tx1), 0.0f);
        float dy = fmaxf(fmaxf(ty0 - v.y, v.y - ty1), 0.0f);
        bool keep = (v.z * fmaf(dx, dx, dy * dy) >= cut);
        unsigned m = __ballot_sync(0xffffffffu, keep);
        masks[r] = m;
        mycnt += __popc(m);
    }
    if (lane == 0) wcnt[wrp] = mycnt;
    __syncthreads();
    int base = 0, total = 0;
#pragma unroll
    for (int w = 0; w < 4; w++) {
        if (w < wrp) base += wcnt[w];
        total += wcnt[w];
    }
    const int nk = total < CAPT ? total : CAPT;
#pragma unroll
    for (int r = 0; r < 16; r++) {
        unsigned m = masks[r];
        if (m & (1u << lane)) {
            int rk = base + __popc(m & ((1u << lane) - 1u));
            if (rk < CAPT) idx[rk] = wrp * 512 + r * 32 + lane;
        }
        base += __popc(m);
    }
    __syncthreads();

    // -- Parallel record gather-write (fixed ascending node order) --
    float4* dst = (float4*)(g_list + (size_t)t * CAPT * 8);
    for (int i = tid; i < nk; i += 128) {
        int p = idx[i];
        float4 v = pc[p];
        float C = v.z;
        dst[2 * i + 0] = make_float4(-2.0f * C * v.x, -2.0f * C * v.y,
                                     C * fmaf(v.x, v.x, v.y * v.y), C);
        dst[2 * i + 1] = make_float4(W2[p], W2[PP + p], W2[2 * PP + p], 0.0f);
    }
    if (tid == 0) g_ncnt[t] = nk;
}

// ---------------------------------------------------------------------------
// K2: per-tile evaluation. 128 threads = 64 query-slots x 2 node-chunks.
// Fixed chunking + fixed reduce order => bitwise-deterministic output.
// ---------------------------------------------------------------------------
__global__ __launch_bounds__(128)
void k_main(float* __restrict__ out) {
    __shared__ float4 sh[2 * CAPT];          // 8 KB records
    __shared__ float4 red[128];
    const int tid = threadIdx.x;
    const int t = blockIdx.x;
    const int nn = g_ncnt[t];
    const int cnt = min(g_qcnt[t], CAPQ);

    const float4* lst = (const float4*)(g_list + (size_t)t * CAPT * 8);
    for (int i = tid; i < 2 * nn; i += 128)
        sh[i] = lst[i];
    __syncthreads();

    const int chunk = tid >> 6;              // 0 or 1
    const int qslot = tid & 63;
    for (int qb = 0; qb < cnt; qb += 64) {
        int qi = qb + qslot;
        float4 acc = make_float4(0.f, 0.f, 0.f, 0.f);
        if (qi < cnt) {
            unsigned d = g_qdat[t * CAPQ + qi];
            float x0 = (float)(d & 255u);
            float x1 = (float)((d >> 8) & 255u);
            float xx = fmaf(x0, x0, x1 * x1);
#pragma unroll 4
            for (int j = chunk; j < nn; j += 2) {
                float4 a = sh[2 * j];
                float4 b = sh[2 * j + 1];
                float arg = fmaf(a.w, xx, a.z);
                arg = fmaf(a.x, x0, arg);
                arg = fmaf(a.y, x1, arg);
                float e = ex2f(arg);
                acc.x += e;
                acc.y = fmaf(e, b.x, acc.y);
                acc.z = fmaf(e, b.y, acc.z);
                acc.w = fmaf(e, b.z, acc.w);
            }
        }
        red[tid] = acc;
        __syncthreads();
        if (tid < 64 && qb + tid < cnt) {
            float4 a0 = red[tid];
            float4 a1 = red[64 + tid];
            float den = a0.x + a1.x;
            float inv = 1.0f / den;
            int q = (int)(g_qdat[t * CAPQ + qb + tid] >> 16);
            out[3 * q + 0] = (a0.y + a1.y) * inv;
            out[3 * q + 1] = (a0.z + a1.z) * inv;
            out[3 * q + 2] = (a0.w + a1.w) * inv;
        }
        __syncthreads();
    }
    if (tid == 0) g_qcnt[t] = 0;             // ready for next graph replay
}

// ---------------------------------------------------------------------------
extern "C" void kernel_launch(void* const* d_in, const int* in_sizes, int n_in,
                              void* d_out, int out_size) {
    const int*   X   = (const int*)d_in[0];     // [N,2] int32
    const int*   pat = (const int*)d_in[1];     // [P,2] int32
    const float* W2  = (const float*)d_in[2];   // [C,P] f32
    const float* sig = (const float*)d_in[3];   // [P]   f32
    float* out = (float*)d_out;
    (void)in_sizes; (void)n_in; (void)out_size;

    k_prep<<<NTILES, 128>>>((const int2*)X, (const int2*)pat, W2, sig);
    k_main<<<NTILES, 128>>>(out);
}